// round 6
// baseline (speedup 1.0000x reference)
#include <cuda_runtime.h>

// Fixed shapes: B=2, D=1024, L=2048, NH=8 -> H=128
#define B_   2
#define D_   1024
#define L_   2048
#define NH   8
#define H_   128
#define TLL  512          // l-tile per block: 128 threads x 4 consecutive l each
#define TM   128          // m-tile
#define KOFF 640          // zeros before lag 0 in g_kf rows
#define KPAD 3136         // padded filter row length
#define KW   648          // k window floats per tile
#define KWP  656          // padded smem k window

typedef unsigned long long u64;

// Forward zero-padded filter and its 1-shifted copy:
//   g_kf [h][KOFF+lag] = k[h][lag] (0 <= lag < L), else 0
//   g_kfs[h][j]        = g_kf[h][j-1] semantics (kval(lag-1))
__device__ __align__(16) float g_kf [H_ * KPAD];
__device__ __align__(16) float g_kfs[H_ * KPAD];
// Element-duplicated copies of v and x2: dup[.., 2m] = dup[.., 2m+1] = src[.., m]
__device__ __align__(16) float g_vdup [B_ * D_ * 2 * L_];
__device__ __align__(16) float g_x2dup[B_ * D_ * 2 * L_];

__device__ __forceinline__ u64 pack2(float x, float y) {
    u64 r; asm("mov.b64 %0, {%1,%2};" : "=l"(r) : "f"(x), "f"(y)); return r;
}
__device__ __forceinline__ float lo2(u64 v) {
    float x, y; asm("mov.b64 {%0,%1}, %2;" : "=f"(x), "=f"(y) : "l"(v)); return x;
}
__device__ __forceinline__ float hi2(u64 v) {
    float x, y; asm("mov.b64 {%0,%1}, %2;" : "=f"(x), "=f"(y) : "l"(v)); return y;
}
__device__ __forceinline__ u64 fma2(u64 a, u64 b, u64 c) {
    u64 d; asm("fma.rn.f32x2 %0, %1, %2, %3;" : "=l"(d) : "l"(a), "l"(b), "l"(c)); return d;
}
__device__ __forceinline__ u64 mul2(u64 a, u64 b) {
    u64 d; asm("mul.rn.f32x2 %0, %1, %2;" : "=l"(d) : "l"(a), "l"(b)); return d;
}
__device__ __forceinline__ u64 ll(double d) { return __double_as_longlong(d); }
__device__ __forceinline__ void cpasync16(void* dst, const void* src) {
    unsigned d = (unsigned)__cvta_generic_to_shared(dst);
    asm volatile("cp.async.ca.shared.global [%0], [%1], 16;" :: "r"(d), "l"(src));
}
__device__ __forceinline__ void cp_commit() {
    asm volatile("cp.async.commit_group;" ::: "memory");
}

__global__ void build_kf2(const float* __restrict__ k) {
    int idx = blockIdx.x * 256 + threadIdx.x;
    if (idx >= H_ * KPAD) return;
    int h = idx / KPAD, j = idx % KPAD;
    int lag = j - KOFF;
    g_kf [idx] = (lag >= 0 && lag < L_)         ? k[h * L_ + lag]       : 0.0f;
    g_kfs[idx] = (lag - 1 >= 0 && lag - 1 < L_) ? k[h * L_ + (lag - 1)] : 0.0f;
}

__global__ void dup_inputs(const float* __restrict__ v, const float* __restrict__ x2) {
    size_t i4 = (size_t)blockIdx.x * 256 + threadIdx.x;   // float4 index
    size_t n4 = (size_t)B_ * D_ * L_ / 4;
    if (i4 >= n4) return;
    float4 a = ((const float4*)v)[i4];
    float4 b = ((const float4*)x2)[i4];
    float4* ov = (float4*)g_vdup  + i4 * 2;
    float4* ox = (float4*)g_x2dup + i4 * 2;
    ov[0] = make_float4(a.x, a.x, a.y, a.y);
    ov[1] = make_float4(a.z, a.z, a.w, a.w);
    ox[0] = make_float4(b.x, b.x, b.y, b.y);
    ox[1] = make_float4(b.z, b.z, b.w, b.w);
}

__global__ void __launch_bounds__(128, 5)
hyena_conv_kernel(const float* __restrict__ v,
                  const float* __restrict__ bias,
                  const float* __restrict__ x1,
                  const float* __restrict__ x2,
                  float* __restrict__ out)
{
    __shared__ __align__(16) float vsm [2][NH][2 * TM];   // duplicated v tile
    __shared__ __align__(16) float x2sm[2][NH][2 * TM];   // duplicated x2 tile
    __shared__ __align__(16) float ka[2][KWP];            // kval(base-128+s)
    __shared__ __align__(16) float kb[2][KWP];            // kval(base-128+s-1)
    __shared__ float bsm[NH];

    const int tid = threadIdx.x;
    const int wid = tid >> 5;
    const int blk = blockIdx.x;
    const int bh  = blk & 255;            // b*H_ + h
    const int lt  = 3 - (blk >> 8);       // LPT: heavy l-tiles first
    const int h   = bh & 127;
    const int b   = bh >> 7;
    const int L0  = lt * TLL;
    const int l0  = L0 + 4 * tid;         // this thread's 4 l's

    const float* vb   = v  + ((size_t)b * D_ + (size_t)h * NH) * L_;
    const float* x1b  = x1 + ((size_t)b * D_ + (size_t)h * NH) * L_;
    const float* x2b  = x2 + ((size_t)b * D_ + (size_t)h * NH) * L_;
    float*       ob   = out + ((size_t)b * D_ + (size_t)h * NH) * L_;
    const float* vdb  = g_vdup  + ((size_t)b * D_ + (size_t)h * NH) * 2 * L_;
    const float* xdb  = g_x2dup + ((size_t)b * D_ + (size_t)h * NH) * 2 * L_;
    const float* kfb  = g_kf  + (size_t)h * KPAD + (KOFF - 128 + L0);
    const float* kfsb = g_kfs + (size_t)h * KPAD + (KOFF - 128 + L0);

    const int nmt = (L0 + TLL) / TM;      // 4,8,12,16

    auto issue = [&](int mt_) {
        const int p  = mt_ & 1;
        const int M0 = mt_ * TM;
        #pragma unroll
        for (int q = 0; q < 4; q++) {
            int f = tid + 128 * q;            // 0..511 chunk id
            int i = f >> 6, c = (f & 63) << 2;
            cpasync16(&vsm [p][i][c], vdb + (size_t)i * 2 * L_ + 2 * M0 + c);
            cpasync16(&x2sm[p][i][c], xdb + (size_t)i * 2 * L_ + 2 * M0 + c);
        }
        #pragma unroll
        for (int q = 0; q < 2; q++) {
            int f = tid + 128 * q;
            if (f < KW / 4) {
                cpasync16(&ka[p][f * 4], kfb  - M0 + f * 4);
                cpasync16(&kb[p][f * 4], kfsb - M0 + f * 4);
            }
        }
        cp_commit();
    };

    issue(0);
    if (nmt > 1) issue(1);

    if (tid < NH) bsm[tid] = bias[h * NH + tid];

    // x1 gates as natural packed pairs: (l0,l0+1) and (l0+2,l0+3) — no splats
    u64 x1a[NH], x1c[NH];
    #pragma unroll
    for (int i = 0; i < NH; i++) {
        float4 q = *(const float4*)&x1b[i * L_ + l0];
        x1a[i] = pack2(q.x, q.y);
        x1c[i] = pack2(q.z, q.w);
    }

    u64 acc0[NH], acc1[NH];   // acc lanes = (l0,l0+1) / (l0+2,l0+3)
    #pragma unroll
    for (int j = 0; j < NH; j++) { acc0[j] = 0; acc1[j] = 0; }

    for (int mt = 0; mt < nmt; mt++) {
        if (mt == nmt - 1) asm volatile("cp.async.wait_group 0;" ::: "memory");
        else               asm volatile("cp.async.wait_group 1;" ::: "memory");
        __syncthreads();

        const int p    = mt & 1;
        const int base = L0 - mt * TM;
        // per-warp triangular bound: taps all zero for mm >= base + 128*wid + 128
        const int mmax = min(TM, base + 128 * wid + 128);

        if (mmax > 0) {
            const float* vrow = &vsm[p][0][0];
            const float* xrow = &x2sm[p][0][0];
            const float* kap  = &ka[p][4 * tid + 128];
            const float* kbp  = &kb[p][4 * tid + 128];

            #pragma unroll 2
            for (int mm = 0; mm < mmax; mm += 2) {
                // s = A[l-pairs, m] and A[l-pairs, m+1] via duplicated-v splats
                u64 s0m, s1m, s0n, s1n;
                {
                    double2 vq = *(const double2*)(vrow + 2 * mm);  // (v_m,v_m,v_m1,v_m1)
                    u64 vm = ll(vq.x), vn = ll(vq.y);
                    s0m = mul2(x1a[0], vm); s1m = mul2(x1c[0], vm);
                    s0n = mul2(x1a[0], vn); s1n = mul2(x1c[0], vn);
                }
                #pragma unroll
                for (int i = 1; i < NH; i++) {
                    double2 vq = *(const double2*)(vrow + i * 2 * TM + 2 * mm);
                    u64 vm = ll(vq.x), vn = ll(vq.y);
                    s0m = fma2(x1a[i], vm, s0m); s1m = fma2(x1c[i], vm, s1m);
                    s0n = fma2(x1a[i], vn, s0n); s1n = fma2(x1c[i], vn, s1n);
                }

                // Toeplitz taps: aligned LDS.64 pairs, zero pack/ALU
                u64 ta0 = *(const u64*)(kap - mm);        // (k[lag],  k[lag+1])   m,   lanes l0..
                u64 ta1 = *(const u64*)(kap - mm + 2);    //                        m,   lanes l0+2..
                u64 tb0 = *(const u64*)(kbp - mm);        // (k[lag-1],k[lag])     m+1
                u64 tb1 = *(const u64*)(kbp - mm + 2);
                u64 t0m = mul2(s0m, ta0), t1m = mul2(s1m, ta1);
                u64 t0n = mul2(s0n, tb0), t1n = mul2(s1n, tb1);

                // acc[j] += t * x2splat (duplicated-x2 smem)
                #pragma unroll
                for (int j = 0; j < NH; j++) {
                    double2 xq = *(const double2*)(xrow + j * 2 * TM + 2 * mm);
                    u64 xm = ll(xq.x), xn = ll(xq.y);
                    acc0[j] = fma2(t0m, xm, acc0[j]);
                    acc1[j] = fma2(t1m, xm, acc1[j]);
                    acc0[j] = fma2(t0n, xn, acc0[j]);
                    acc1[j] = fma2(t1n, xn, acc1[j]);
                }
            }
        }

        __syncthreads();
        if (mt + 2 < nmt) issue(mt + 2);
    }

    // Epilogue: skip/bias term + vectorized float4 store.
    float sb0 = 0.f, sb1 = 0.f, sb2 = 0.f, sb3 = 0.f;
    #pragma unroll
    for (int i = 0; i < NH; i++) {
        float4 vv = *(const float4*)&vb[i * L_ + l0];
        float bw = bsm[i];
        sb0 += lo2(x1a[i]) * bw * vv.x;
        sb1 += hi2(x1a[i]) * bw * vv.y;
        sb2 += lo2(x1c[i]) * bw * vv.z;
        sb3 += hi2(x1c[i]) * bw * vv.w;
    }
    #pragma unroll
    for (int j = 0; j < NH; j++) {
        float4 xx = *(const float4*)&x2b[j * L_ + l0];
        float4 o;
        o.x = lo2(acc0[j]) + sb0 * xx.x;
        o.y = hi2(acc0[j]) + sb1 * xx.y;
        o.z = lo2(acc1[j]) + sb2 * xx.z;
        o.w = hi2(acc1[j]) + sb3 * xx.w;
        *(float4*)&ob[j * L_ + l0] = o;
    }
}

extern "C" void kernel_launch(void* const* d_in, const int* in_sizes, int n_in,
                              void* d_out, int out_size)
{
    const float* v    = (const float*)d_in[0];
    const float* k    = (const float*)d_in[1];
    const float* bias = (const float*)d_in[2];
    const float* x1   = (const float*)d_in[3];
    const float* x2   = (const float*)d_in[4];
    float* out = (float*)d_out;

    build_kf2<<<(H_ * KPAD + 255) / 256, 256>>>(k);
    dup_inputs<<<(B_ * D_ * L_ / 4 + 255) / 256, 256>>>(v, x2);
    dim3 grid(B_ * H_ * (L_ / TLL));   // 1024 blocks, heavy l-tiles first
    hyena_conv_kernel<<<grid, 128>>>(v, bias, x1, x2, out);
}

// round 7
// speedup vs baseline: 1.4531x; 1.4531x over previous
#include <cuda_runtime.h>

// Fixed shapes: B=2, D=1024, L=2048, NH=8 -> H=128
#define B_   2
#define D_   1024
#define L_   2048
#define NH   8
#define H_   128
#define TLL  256          // l-tile per block: 128 threads x 2 l (l0=L0+2t, l1=l0+1)
#define TM   128          // m-tile
#define KR2  2720         // padded reversed-filter row length
#define KWIN 400          // k smem window floats per stage per copy
#define NST  3            // pipeline stages

typedef unsigned long long u64;

// Reversed zero-padded filter copies:
//   g_kra[h][u] = kval(h, 2306 - u),  g_krb[h][u] = kval(h, 2307 - u)
// where kval(h,a) = k[h][a] for 0<=a<L, else 0.
__device__ __align__(16) float g_kra[H_ * KR2];
__device__ __align__(16) float g_krb[H_ * KR2];

__device__ __forceinline__ u64 pack2(float x, float y) {
    u64 r; asm("mov.b64 %0, {%1,%2};" : "=l"(r) : "f"(x), "f"(y)); return r;
}
__device__ __forceinline__ float hsum2(u64 v) {
    float x, y; asm("mov.b64 {%0,%1}, %2;" : "=f"(x), "=f"(y) : "l"(v)); return x + y;
}
__device__ __forceinline__ u64 fma2(u64 a, u64 b, u64 c) {
    u64 d; asm("fma.rn.f32x2 %0, %1, %2, %3;" : "=l"(d) : "l"(a), "l"(b), "l"(c)); return d;
}
__device__ __forceinline__ u64 mul2(u64 a, u64 b) {
    u64 d; asm("mul.rn.f32x2 %0, %1, %2;" : "=l"(d) : "l"(a), "l"(b)); return d;
}
__device__ __forceinline__ u64 ll(double d) { return __double_as_longlong(d); }
__device__ __forceinline__ void cpasync16(void* dst, const void* src) {
    unsigned d = (unsigned)__cvta_generic_to_shared(dst);
    asm volatile("cp.async.ca.shared.global [%0], [%1], 16;" :: "r"(d), "l"(src));
}

__global__ void build_kr(const float* __restrict__ k) {
    int idx = blockIdx.x * 256 + threadIdx.x;
    if (idx >= H_ * KR2) return;
    int h = idx / KR2, u = idx % KR2;
    int a  = (L_ + 258) - u;       // 2306 - u
    int a2 = a + 1;                // 2307 - u
    g_kra[idx] = (a  >= 0 && a  < L_) ? k[h * L_ + a ] : 0.0f;
    g_krb[idx] = (a2 >= 0 && a2 < L_) ? k[h * L_ + a2] : 0.0f;
}

__global__ void __launch_bounds__(128, 5)
hyena_conv_kernel(const float* __restrict__ v,
                  const float* __restrict__ bias,
                  const float* __restrict__ x1,
                  const float* __restrict__ x2,
                  float* __restrict__ out)
{
    __shared__ __align__(16) float vsm [NST][NH][TM];   // [stage][i][m]
    __shared__ __align__(16) float x2sm[NST][NH][TM];   // [stage][j][m]
    __shared__ __align__(16) float wa[NST][KWIN];       // taps for l0 lanes
    __shared__ __align__(16) float wb[NST][KWIN];       // taps for l1 lanes
    __shared__ float bsm[NH];

    const int tid = threadIdx.x;
    const int wid = tid >> 5;
    const int blk = blockIdx.x;
    const int bh  = blk & 255;            // b*H_ + h
    const int lt  = 7 - (blk >> 8);       // LPT: heavy l-tiles first
    const int h   = bh & 127;
    const int b   = bh >> 7;
    const int L0  = lt * TLL;
    const int l0  = L0 + 2 * tid;         // this thread's l's: l0, l0+1

    const float* vb  = v  + ((size_t)b * D_ + (size_t)h * NH) * L_;
    const float* x1b = x1 + ((size_t)b * D_ + (size_t)h * NH) * L_;
    const float* x2b = x2 + ((size_t)b * D_ + (size_t)h * NH) * L_;
    float*       ob  = out + ((size_t)b * D_ + (size_t)h * NH) * L_;
    const float* kra = g_kra + (size_t)h * KR2;
    const float* krb = g_krb + (size_t)h * KR2;

    const int nmt = L0 / TM + 2;          // causal m-tiles: 2..16

    const int c0i = tid >> 5,         c0m = (tid & 31) << 2;
    const int c1i = (tid + 128) >> 5, c1m = (tid & 31) << 2;
    auto issue = [&](int mt_) {
        const int p  = mt_ % NST;
        const int M0 = mt_ * TM;
        cpasync16(&vsm [p][c0i][c0m], vb  + c0i * L_ + M0 + c0m);
        cpasync16(&x2sm[p][c0i][c0m], x2b + c0i * L_ + M0 + c0m);
        cpasync16(&vsm [p][c1i][c1m], vb  + c1i * L_ + M0 + c1m);
        cpasync16(&x2sm[p][c1i][c1m], x2b + c1i * L_ + M0 + c1m);
        // k windows: wa[p][s] = kra[u0+s], u0 = 2048 - L0 + M0 (16B aligned)
        const int u0 = L_ - L0 + M0;
        if (tid < KWIN / 4) {
            cpasync16(&wa[p][tid * 4], kra + u0 + tid * 4);
            cpasync16(&wb[p][tid * 4], krb + u0 + tid * 4);
        }
        asm volatile("cp.async.commit_group;" ::: "memory");
    };

    issue(0);
    issue(1);

    if (tid < NH) bsm[tid] = bias[h * NH + tid];

    // x1 gate splats for l0, l1 (prologue-only ALU)
    u64 x1A[NH], x1B[NH];
    float x1v0[NH], x1v1[NH];
    #pragma unroll
    for (int i = 0; i < NH; i++) {
        float2 q = *(const float2*)&x1b[i * L_ + l0];
        x1A[i] = pack2(q.x, q.x);
        x1B[i] = pack2(q.y, q.y);
        x1v0[i] = q.x; x1v1[i] = q.y;
    }

    u64 accA[NH], accB[NH];   // lanes = (even m, odd m) partial sums
    #pragma unroll
    for (int j = 0; j < NH; j++) { accA[j] = 0; accB[j] = 0; }

    const int soff = 258 - 2 * tid;   // tap window index base (even, >= 4)

    for (int mt = 0; mt < nmt; mt++) {
        if (mt == nmt - 1) asm volatile("cp.async.wait_group 0;" ::: "memory");
        else               asm volatile("cp.async.wait_group 1;" ::: "memory");
        __syncthreads();              // single barrier per tile

        const int p    = mt % NST;
        const int base = L0 - mt * TM;
        // per-warp triangular bound: taps zero for mm >= base + 64*wid + 64
        const int mmaxw = min(TM, base + 64 * wid + 64);

        if (mmaxw > 0) {
            const float (*vt)[TM]  = vsm[p];
            const float (*x2t)[TM] = x2sm[p];
            const float* kap = &wa[p][soff];
            const float* kbp = &wb[p][soff];

            #pragma unroll 2
            for (int mm = 0; mm < mmaxw; mm += 4) {
                // s[l][mpair] = sum_i x1[i,l] * v[i, m-pair]
                u64 sA0, sA1, sB0, sB1;
                {
                    double2 vq = *(const double2*)&vt[0][mm];
                    u64 vlo = ll(vq.x), vhi = ll(vq.y);
                    sA0 = mul2(x1A[0], vlo); sA1 = mul2(x1A[0], vhi);
                    sB0 = mul2(x1B[0], vlo); sB1 = mul2(x1B[0], vhi);
                }
                #pragma unroll
                for (int i = 1; i < NH; i++) {
                    double2 vq = *(const double2*)&vt[i][mm];
                    u64 vlo = ll(vq.x), vhi = ll(vq.y);
                    sA0 = fma2(x1A[i], vlo, sA0); sA1 = fma2(x1A[i], vhi, sA1);
                    sB0 = fma2(x1B[i], vlo, sB0); sB1 = fma2(x1B[i], vhi, sB1);
                }

                // Toeplitz taps: aligned LDS.64 pairs, zero ALU.
                // wa[soff+mm]   = (k[l0-M0-mm],   k[l0-M0-mm-1])   for lanes (mm, mm+1)
                // wb[soff+mm]   = (k[l1-M0-mm],   k[l1-M0-mm-1])
                u64 tA0 = mul2(*(const u64*)(kap + mm),     sA0);
                u64 tA1 = mul2(*(const u64*)(kap + mm + 2), sA1);
                u64 tB0 = mul2(*(const u64*)(kbp + mm),     sB0);
                u64 tB1 = mul2(*(const u64*)(kbp + mm + 2), sB1);

                // acc[l][j] += t[l] .* x2[j, m-pairs]
                #pragma unroll
                for (int j = 0; j < NH; j++) {
                    double2 xq = *(const double2*)&x2t[j][mm];
                    u64 xlo = ll(xq.x), xhi = ll(xq.y);
                    accA[j] = fma2(tA0, xlo, accA[j]);
                    accB[j] = fma2(tB0, xlo, accB[j]);
                    accA[j] = fma2(tA1, xhi, accA[j]);
                    accB[j] = fma2(tB1, xhi, accB[j]);
                }
            }
        }

        if (mt + 2 < nmt) issue(mt + 2);   // stage free: consumed at mt-1, fenced by top barrier
    }

    // Epilogue: horizontal add + skip/bias term, float2 stores.
    float sbA = 0.f, sbB = 0.f;
    #pragma unroll
    for (int i = 0; i < NH; i++) {
        float2 vv = *(const float2*)&vb[i * L_ + l0];
        float bw = bsm[i];
        sbA += x1v0[i] * bw * vv.x;
        sbB += x1v1[i] * bw * vv.y;
    }
    #pragma unroll
    for (int j = 0; j < NH; j++) {
        float2 xx = *(const float2*)&x2b[j * L_ + l0];
        float2 o;
        o.x = hsum2(accA[j]) + sbA * xx.x;
        o.y = hsum2(accB[j]) + sbB * xx.y;
        *(float2*)&ob[j * L_ + l0] = o;
    }
}

extern "C" void kernel_launch(void* const* d_in, const int* in_sizes, int n_in,
                              void* d_out, int out_size)
{
    const float* v    = (const float*)d_in[0];
    const float* k    = (const float*)d_in[1];
    const float* bias = (const float*)d_in[2];
    const float* x1   = (const float*)d_in[3];
    const float* x2   = (const float*)d_in[4];
    float* out = (float*)d_out;

    build_kr<<<(H_ * KR2 + 255) / 256, 256>>>(k);
    dim3 grid(B_ * H_ * (L_ / TLL));   // 2048 blocks, heavy l-tiles first
    hyena_conv_kernel<<<grid, 128>>>(v, bias, x1, x2, out);
}

// round 8
// speedup vs baseline: 1.5285x; 1.0519x over previous
#include <cuda_runtime.h>

// Fixed shapes: B=2, D=1024, L=2048, NH=8 -> H=128
#define B_   2
#define D_   1024
#define L_   2048
#define NH   8
#define H_   128
#define TLL  256          // l-tile per block: 128 threads x 2 l (l0=L0+2t, l1=l0+1)
#define TM   128          // m-tile
#define KR2  2720         // padded reversed-filter row length
#define KWIN 400          // k smem window floats per stage per copy
#define NST  3            // pipeline stages

typedef unsigned long long u64;

// Reversed zero-padded filter copies:
//   g_kra[h][u] = kval(h, 2306 - u),  g_krb[h][u] = kval(h, 2307 - u)
// where kval(h,a) = k[h][a] for 0<=a<L, else 0.
__device__ __align__(16) float g_kra[H_ * KR2];
__device__ __align__(16) float g_krb[H_ * KR2];

__device__ __forceinline__ u64 pack2(float x, float y) {
    u64 r; asm("mov.b64 %0, {%1,%2};" : "=l"(r) : "f"(x), "f"(y)); return r;
}
__device__ __forceinline__ float hsum2(u64 v) {
    float x, y; asm("mov.b64 {%0,%1}, %2;" : "=f"(x), "=f"(y) : "l"(v)); return x + y;
}
__device__ __forceinline__ u64 fma2(u64 a, u64 b, u64 c) {
    u64 d; asm("fma.rn.f32x2 %0, %1, %2, %3;" : "=l"(d) : "l"(a), "l"(b), "l"(c)); return d;
}
__device__ __forceinline__ u64 mul2(u64 a, u64 b) {
    u64 d; asm("mul.rn.f32x2 %0, %1, %2;" : "=l"(d) : "l"(a), "l"(b)); return d;
}
__device__ __forceinline__ u64 ll(double d) { return __double_as_longlong(d); }
__device__ __forceinline__ void cpasync16(void* dst, const void* src) {
    unsigned d = (unsigned)__cvta_generic_to_shared(dst);
    asm volatile("cp.async.ca.shared.global [%0], [%1], 16;" :: "r"(d), "l"(src));
}

__global__ void build_kr(const float* __restrict__ k) {
    int idx = blockIdx.x * 256 + threadIdx.x;
    if (idx >= H_ * KR2) return;
    int h = idx / KR2, u = idx % KR2;
    int a  = (L_ + 258) - u;       // 2306 - u
    int a2 = a + 1;                // 2307 - u
    g_kra[idx] = (a  >= 0 && a  < L_) ? k[h * L_ + a ] : 0.0f;
    g_krb[idx] = (a2 >= 0 && a2 < L_) ? k[h * L_ + a2] : 0.0f;
}

__global__ void __launch_bounds__(128, 5)
hyena_conv_kernel(const float* __restrict__ v,
                  const float* __restrict__ bias,
                  const float* __restrict__ x1,
                  const float* __restrict__ x2,
                  float* __restrict__ out)
{
    __shared__ __align__(16) float vsm [NST][NH][TM];   // [stage][i][m]
    __shared__ __align__(16) float x2sm[NST][NH][TM];   // [stage][j][m]
    __shared__ __align__(16) float wa[NST][KWIN];       // taps for l0 lanes
    __shared__ __align__(16) float wb[NST][KWIN];       // taps for l1 lanes
    __shared__ float bsm[NH];

    const int tid = threadIdx.x;
    const int wid = tid >> 5;
    const int blk = blockIdx.x;
    const int bh  = blk & 255;            // b*H_ + h
    const int lt  = 7 - (blk >> 8);       // LPT: heavy l-tiles first
    const int h   = bh & 127;
    const int b   = bh >> 7;
    const int L0  = lt * TLL;
    const int l0  = L0 + 2 * tid;         // this thread's l's: l0, l0+1

    const float* vb  = v  + ((size_t)b * D_ + (size_t)h * NH) * L_;
    const float* x1b = x1 + ((size_t)b * D_ + (size_t)h * NH) * L_;
    const float* x2b = x2 + ((size_t)b * D_ + (size_t)h * NH) * L_;
    float*       ob  = out + ((size_t)b * D_ + (size_t)h * NH) * L_;
    const float* kra = g_kra + (size_t)h * KR2;
    const float* krb = g_krb + (size_t)h * KR2;

    const int nmt = L0 / TM + 2;          // causal m-tiles: 2..16

    const int c0i = tid >> 5,         c0m = (tid & 31) << 2;
    const int c1i = (tid + 128) >> 5, c1m = (tid & 31) << 2;
    auto issue = [&](int mt_) {
        const int p  = mt_ % NST;
        const int M0 = mt_ * TM;
        cpasync16(&vsm [p][c0i][c0m], vb  + c0i * L_ + M0 + c0m);
        cpasync16(&x2sm[p][c0i][c0m], x2b + c0i * L_ + M0 + c0m);
        cpasync16(&vsm [p][c1i][c1m], vb  + c1i * L_ + M0 + c1m);
        cpasync16(&x2sm[p][c1i][c1m], x2b + c1i * L_ + M0 + c1m);
        // k windows: wa[p][s] = kra[u0+s], u0 = 2048 - L0 + M0 (16B aligned)
        const int u0 = L_ - L0 + M0;
        if (tid < KWIN / 4) {
            cpasync16(&wa[p][tid * 4], kra + u0 + tid * 4);
            cpasync16(&wb[p][tid * 4], krb + u0 + tid * 4);
        }
        asm volatile("cp.async.commit_group;" ::: "memory");
    };

    issue(0);
    issue(1);

    if (tid < NH) bsm[tid] = bias[h * NH + tid];

    // x1 gate splats for l0, l1 (prologue-only ALU)
    u64 x1A[NH], x1B[NH];
    float x1v0[NH], x1v1[NH];
    #pragma unroll
    for (int i = 0; i < NH; i++) {
        float2 q = *(const float2*)&x1b[i * L_ + l0];
        x1A[i] = pack2(q.x, q.x);
        x1B[i] = pack2(q.y, q.y);
        x1v0[i] = q.x; x1v1[i] = q.y;
    }

    u64 accA[NH], accB[NH];   // lanes = (even m, odd m) partial sums
    #pragma unroll
    for (int j = 0; j < NH; j++) { accA[j] = 0; accB[j] = 0; }

    const int soff = 258 - 2 * tid;   // tap window index base (even, >= 4)

    for (int mt = 0; mt < nmt; mt++) {
        if (mt == nmt - 1) asm volatile("cp.async.wait_group 0;" ::: "memory");
        else               asm volatile("cp.async.wait_group 1;" ::: "memory");
        __syncthreads();              // single barrier per tile

        const int p    = mt % NST;
        const int base = L0 - mt * TM;
        // per-warp triangular bound: taps zero for mm >= base + 64*wid + 64
        const int mmaxw = min(TM, base + 64 * wid + 64);

        if (mmaxw > 0) {
            const float (*vt)[TM]  = vsm[p];
            const float (*x2t)[TM] = x2sm[p];
            const float* kap = &wa[p][soff];
            const float* kbp = &wb[p][soff];

            #pragma unroll 2
            for (int mm = 0; mm < mmaxw; mm += 4) {
                // s[l][mpair] = sum_i x1[i,l] * v[i, m-pair]
                u64 sA0, sA1, sB0, sB1;
                {
                    double2 vq = *(const double2*)&vt[0][mm];
                    u64 vlo = ll(vq.x), vhi = ll(vq.y);
                    sA0 = mul2(x1A[0], vlo); sA1 = mul2(x1A[0], vhi);
                    sB0 = mul2(x1B[0], vlo); sB1 = mul2(x1B[0], vhi);
                }
                #pragma unroll
                for (int i = 1; i < NH; i++) {
                    double2 vq = *(const double2*)&vt[i][mm];
                    u64 vlo = ll(vq.x), vhi = ll(vq.y);
                    sA0 = fma2(x1A[i], vlo, sA0); sA1 = fma2(x1A[i], vhi, sA1);
                    sB0 = fma2(x1B[i], vlo, sB0); sB1 = fma2(x1B[i], vhi, sB1);
                }

                // Toeplitz taps: aligned LDS.64 pairs, zero ALU.
                // wa[soff+mm]   = (k[l0-M0-mm],   k[l0-M0-mm-1])   for lanes (mm, mm+1)
                // wb[soff+mm]   = (k[l1-M0-mm],   k[l1-M0-mm-1])
                u64 tA0 = mul2(*(const u64*)(kap + mm),     sA0);
                u64 tA1 = mul2(*(const u64*)(kap + mm + 2), sA1);
                u64 tB0 = mul2(*(const u64*)(kbp + mm),     sB0);
                u64 tB1 = mul2(*(const u64*)(kbp + mm + 2), sB1);

                // acc[l][j] += t[l] .* x2[j, m-pairs]
                #pragma unroll
                for (int j = 0; j < NH; j++) {
                    double2 xq = *(const double2*)&x2t[j][mm];
                    u64 xlo = ll(xq.x), xhi = ll(xq.y);
                    accA[j] = fma2(tA0, xlo, accA[j]);
                    accB[j] = fma2(tB0, xlo, accB[j]);
                    accA[j] = fma2(tA1, xhi, accA[j]);
                    accB[j] = fma2(tB1, xhi, accB[j]);
                }
            }
        }

        if (mt + 2 < nmt) issue(mt + 2);   // stage free: consumed at mt-1, fenced by top barrier
    }

    // Epilogue: horizontal add + skip/bias term, float2 stores.
    float sbA = 0.f, sbB = 0.f;
    #pragma unroll
    for (int i = 0; i < NH; i++) {
        float2 vv = *(const float2*)&vb[i * L_ + l0];
        float bw = bsm[i];
        sbA += x1v0[i] * bw * vv.x;
        sbB += x1v1[i] * bw * vv.y;
    }
    #pragma unroll
    for (int j = 0; j < NH; j++) {
        float2 xx = *(const float2*)&x2b[j * L_ + l0];
        float2 o;
        o.x = hsum2(accA[j]) + sbA * xx.x;
        o.y = hsum2(accB[j]) + sbB * xx.y;
        *(float2*)&ob[j * L_ + l0] = o;
    }
}

extern "C" void kernel_launch(void* const* d_in, const int* in_sizes, int n_in,
                              void* d_out, int out_size)
{
    const float* v    = (const float*)d_in[0];
    const float* k    = (const float*)d_in[1];
    const float* bias = (const float*)d_in[2];
    const float* x1   = (const float*)d_in[3];
    const float* x2   = (const float*)d_in[4];
    float* out = (float*)d_out;

    build_kr<<<(H_ * KR2 + 255) / 256, 256>>>(k);
    dim3 grid(B_ * H_ * (L_ / TLL));   // 2048 blocks, heavy l-tiles first
    hyena_conv_kernel<<<grid, 128>>>(v, bias, x1, x2, out);
}